// round 13
// baseline (speedup 1.0000x reference)
#include <cuda_runtime.h>
#include <cuda_fp16.h>
#include <cstdint>
#include <cstddef>

// Problem constants
#define BATCH 512
#define TSTEPS 256
#define HID 512
#define G4 2048
#define DEC_STEPS 42

// Persistent config: 128 CTAs = 8 m-groups x 16 jn. CTA tile 64(m) x 128(n-reord),
// 512 threads (16 warps = 4m x 4n), warp tile 16x32.
// B slice (128 rows x 512 k fp16) resident in smem; full A staged per step.
#define TM 64
#define TNR 128
#define KC 64
#define NKC 8
#define PITCH 144                          // bytes per smem row (72 fp16)
#define BCHUNK (TNR * PITCH)               // 18432
#define BTOT (NKC * BCHUNK)                // 147456
#define ACHUNK (TM * PITCH)                // 9216
#define AOFF BTOT
#define HOFF (BTOT + NKC * ACHUNK)         // 221184: h staging (4KB)
#define SMEM_TOTAL (HOFF + 4096)           // 225280

// ------------------------- device scratch (no allocs) ----------------------
__device__ __align__(128) __half g_wh[G4 * HID];      // fp16 reordered W_hh
__device__ __align__(128) __half g_h0[BATCH * HID];
__device__ __align__(128) __half g_h1[BATCH * HID];
__device__ __align__(128) float g_xT[TSTEPS * BATCH]; // transposed x
__device__ float g_hf[BATCH * HID];
__device__ float g_c [BATCH * HID];
__device__ float g_G0[BATCH * G4];
__device__ float g_br[G4];
__device__ float g_wihr[G4];
__device__ __align__(128) unsigned g_flags[128];      // per-CTA h-ready flags

// ------------------------------ helpers ------------------------------------
__device__ __forceinline__ uint32_t smem_u32(const void* p) {
    uint32_t a;
    asm("{ .reg .u64 t; cvta.to.shared.u64 t, %1; cvt.u32.u64 %0, t; }" : "=r"(a) : "l"(p));
    return a;
}
__device__ __forceinline__ void cpasync16(uint32_t s, const void* g) {
    asm volatile("cp.async.cg.shared.global [%0], [%1], 16;" :: "r"(s), "l"(g));
}
__device__ __forceinline__ void cpasync_commit() {
    asm volatile("cp.async.commit_group;" ::: "memory");
}
template <int N> __device__ __forceinline__ void cpasync_wait() {
    asm volatile("cp.async.wait_group %0;" :: "n"(N) : "memory");
}
__device__ __forceinline__ void ldsm_x4(uint32_t* r, uint32_t addr) {
    asm volatile("ldmatrix.sync.aligned.m8n8.x4.shared.b16 {%0,%1,%2,%3}, [%4];"
                 : "=r"(r[0]), "=r"(r[1]), "=r"(r[2]), "=r"(r[3]) : "r"(addr));
}
__device__ __forceinline__ void mma16816(float* c, const uint32_t* a, uint32_t b0, uint32_t b1) {
    asm volatile(
        "mma.sync.aligned.m16n8k16.row.col.f32.f16.f16.f32 "
        "{%0,%1,%2,%3}, {%4,%5,%6,%7}, {%8,%9}, {%0,%1,%2,%3};"
        : "+f"(c[0]), "+f"(c[1]), "+f"(c[2]), "+f"(c[3])
        : "r"(a[0]), "r"(a[1]), "r"(a[2]), "r"(a[3]), "r"(b0), "r"(b1));
}
// release/acquire primitives (no full membar)
__device__ __forceinline__ void st_release(unsigned* p, unsigned v) {
    asm volatile("st.release.gpu.global.u32 [%0], %1;" :: "l"(p), "r"(v) : "memory");
}
__device__ __forceinline__ unsigned ld_acquire(const unsigned* p) {
    unsigned v;
    asm volatile("ld.acquire.gpu.global.u32 %0, [%1];" : "=r"(v) : "l"(p) : "memory");
    return v;
}
// fast transcendental (MUFU.EX2 based); per-op rel err ~1e-6
__device__ __forceinline__ float fsigm(float v) {
    return __fdividef(1.0f, 1.0f + __expf(-v));
}
__device__ __forceinline__ float ftanh(float v) {
    v = fminf(fmaxf(v, -15.0f), 15.0f);
    float e = __expf(2.0f * v);
    return __fdividef(e - 1.0f, e + 1.0f);
}

// -------------------------- init / prep kernels -----------------------------
__global__ void init_state(uint32_t* h0, const float* __restrict__ x,
                           float* __restrict__ xT) {
    int i = blockIdx.x * 256 + threadIdx.x;
    if (i < BATCH * HID / 2) h0[i] = 0u;
    if (i < TSTEPS * BATCH) {
        int t = i >> 9, b = i & 511;         // xT[t*512+b] = x[b*256+t]
        xT[i] = x[b * TSTEPS + t];
    }
    if (i < 128) g_flags[i] = 0u;
}

// Convert W_hh to fp16 with per-column gate interleave:
//   old row r = q*512 + col, col = jn*32 + s  ->  new row = jn*128 + s*4 + q
__global__ void wprep(const float* __restrict__ Whh,
                      const float* __restrict__ b_ih, const float* __restrict__ b_hh,
                      const float* __restrict__ Wih,
                      __half* __restrict__ wh,
                      float* __restrict__ br, float* __restrict__ wihr)
{
    int i = blockIdx.x * 256 + threadIdx.x;
    if (i >= G4 * HID) return;
    int old_r = i / HID;
    int k = i - old_r * HID;
    int q = old_r >> 9;
    int col = old_r & 511;
    int jn = col >> 5;
    int s = col & 31;
    int new_r = jn * 128 + s * 4 + q;
    wh[new_r * HID + k] = __float2half(Whh[i]);
    if (k == 0) {
        br[new_r] = b_ih[old_r] + b_hh[old_r];
        wihr[new_r] = Wih[old_r];
    }
}

// ----------------------- persistent encoder kernel --------------------------
__global__ __launch_bounds__(512, 1)
void lstm_persist(const __half* __restrict__ wh,
                  const float* __restrict__ br, const float* __restrict__ wihr,
                  const float* __restrict__ xT,
                  __half* __restrict__ h0g, __half* __restrict__ h1g,
                  float* __restrict__ hf, float* __restrict__ cg,
                  float* __restrict__ G0)
{
    extern __shared__ __align__(16) char smem[];
    const uint32_t sb = smem_u32(smem);
    const int tid = threadIdx.x;
    const int wid = tid >> 5;
    const int l = tid & 31;
    const int wm = wid & 3;               // 0..3: 16-row m tile
    const int wn = wid >> 2;              // 0..3: 32-col n tile
    const int jn = blockIdx.x & 15;       // 0..15 (32 logical cols each)
    const int mg = blockIdx.x >> 4;       // 0..7  m-group
    const int m0 = mg * TM;
    const int n0 = jn * TNR;              // reordered W row base

    // ---- load resident B slice (128 rows x 512 k), chunked by KC ----
#pragma unroll
    for (int it = 0; it < 16; ++it) {
        int slot = tid + it * 512;        // 0..8191
        int seg = slot & 7;
        int r = (slot >> 3) & 127;
        int kc = slot >> 10;
        cpasync16(sb + (uint32_t)(kc * BCHUNK + r * PITCH + seg * 16),
                  (const char*)wh + ((size_t)(n0 + r) * HID + kc * KC) * 2 + seg * 16);
    }
    cpasync_commit();
    cpasync_wait<0>();
    __syncthreads();

    // per-lane ldmatrix byte offsets
    const uint32_t aoff = (uint32_t)((l & 15) * PITCH + (l >> 4) * 16);
    const uint32_t boff = (uint32_t)(((l & 7) + ((l >> 4) << 3)) * PITCH + ((l >> 3) & 1) * 16);

    // epilogue cell mapping (fixed across steps): c in registers
    const int erl = wm * 16 + (l >> 2) + ((l & 1) ? 8 : 0);   // local row 0..63
    const int erow = m0 + erl;
    float creg[4] = {0.f, 0.f, 0.f, 0.f};

    // preload per-thread bias / W_ih constants (fixed across steps)
    float4 bqr[4], wqr[4];
    int scolr[4];
#pragma unroll
    for (int nt = 0; nt < 4; ++nt) {
        int scol = wn * 8 + nt * 2 + ((l & 3) >> 1);
        scolr[nt] = scol;
        bqr[nt] = *reinterpret_cast<const float4*>(&br[n0 + scol * 4]);
        wqr[nt] = *reinterpret_cast<const float4*>(&wihr[n0 + scol * 4]);
    }

    unsigned* flags = &g_flags[mg * 16];
    __half* shh = reinterpret_cast<__half*>(smem + HOFF);

#pragma unroll 1
    for (int t = 0; t <= TSTEPS; ++t) {
        const __half* hin = (t & 1) ? h1g : h0g;
        __half* hout      = (t & 1) ? h0g : h1g;

        // ---- stage full A (64 x 512) in two halves, gated by producer flags.
        // Half h needs chunks 4h..4h+3, produced by CTAs jn = 8h..8h+7.
        // Lanes 0..7 of every warp spin on those 8 flags (>= t). No CTA-wide
        // sync needed: each warp gates only its own cp.async issues.
#pragma unroll
        for (int half = 0; half < 2; ++half) {
            if (t > 0) {
                if (l < 8) {
                    const unsigned* f = &flags[half * 8 + l];
                    while (ld_acquire(f) < (unsigned)t) { }
                }
                __syncwarp();
            }
#pragma unroll
            for (int it = 0; it < 4; ++it) {
                int slot = tid + it * 512;           // 0..2047
                int seg = slot & 7;
                int r = (slot >> 3) & 63;
                int kc = half * 4 + it;
                cpasync16(sb + AOFF + (uint32_t)(kc * ACHUNK + r * PITCH + seg * 16),
                          (const char*)hin + ((size_t)(m0 + r) * HID + kc * KC) * 2 + seg * 16);
            }
            cpasync_commit();
        }

        float acc[4][4];
#pragma unroll
        for (int nt = 0; nt < 4; ++nt)
#pragma unroll
            for (int v = 0; v < 4; ++v) acc[nt][v] = 0.0f;

        // ---- MMA: half 0 while half 1 lands, then half 1 ----
#pragma unroll
        for (int half = 0; half < 2; ++half) {
            if (half == 0) cpasync_wait<1>(); else cpasync_wait<0>();
            __syncthreads();
#pragma unroll
            for (int kci = 0; kci < 4; ++kci) {
                int kc = half * 4 + kci;
                const uint32_t stA = sb + AOFF + (uint32_t)(kc * ACHUNK + wm * 16 * PITCH);
                const uint32_t stB = sb + (uint32_t)(kc * BCHUNK + wn * 32 * PITCH);
#pragma unroll
                for (int ks = 0; ks < 4; ++ks) {
                    const uint32_t ka = (uint32_t)(ks * 32);   // 16 fp16 = 32B
                    uint32_t ar[4], b0r[4], b1r[4];
                    ldsm_x4(ar, stA + ka + aoff);
                    ldsm_x4(b0r, stB + ka + boff);
                    ldsm_x4(b1r, stB + (uint32_t)(16 * PITCH) + ka + boff);
                    mma16816(acc[0], ar, b0r[0], b0r[1]);
                    mma16816(acc[1], ar, b0r[2], b0r[3]);
                    mma16816(acc[2], ar, b1r[0], b1r[1]);
                    mma16816(acc[3], ar, b1r[2], b1r[3]);
                }
            }
        }

        // ---------------- register epilogue (shfl gate gather) ---------------
        // acc[nt] col n_local = wn*32 + nt*8 + (l&3)*2 (+1) = s*4 + q.
        // Lanes l, l^1 hold (i,f)/(g,o) of the same logical column.
        if (t < TSTEPS) {
            const float xv = xT[t * BATCH + erow];
#pragma unroll
            for (int nt = 0; nt < 4; ++nt) {
                float p0 = __shfl_xor_sync(0xffffffffu, acc[nt][0], 1);
                float p1 = __shfl_xor_sync(0xffffffffu, acc[nt][1], 1);
                float p2 = __shfl_xor_sync(0xffffffffu, acc[nt][2], 1);
                float p3 = __shfl_xor_sync(0xffffffffu, acc[nt][3], 1);
                float gi, gf, gg, go;
                if ((l & 1) == 0) { gi = acc[nt][0]; gf = acc[nt][1]; gg = p0; go = p1; }
                else              { gi = p2; gf = p3; gg = acc[nt][2]; go = acc[nt][3]; }
                gi += bqr[nt].x + xv * wqr[nt].x;
                gf += bqr[nt].y + xv * wqr[nt].y;
                gg += bqr[nt].z + xv * wqr[nt].z;
                go += bqr[nt].w + xv * wqr[nt].w;
                float cn = fsigm(gf) * creg[nt] + fsigm(gi) * ftanh(gg);
                creg[nt] = cn;
                float hv = fsigm(go) * ftanh(cn);
                shh[erl * 32 + scolr[nt]] = __float2half(hv);
                if (t == TSTEPS - 1) {
                    int idx = erow * HID + jn * 32 + scolr[nt];
                    hf[idx] = hv; cg[idx] = cn;
                }
            }
            __syncthreads();
            // coalesced copy-out: 64 rows x 32 halfs (64B/row), 512 x 8B STG
            {
                int r = tid >> 3, seg = tid & 7;
                *reinterpret_cast<uint64_t*>(&hout[(m0 + r) * HID + jn * 32 + seg * 4]) =
                    *reinterpret_cast<const uint64_t*>(smem + HOFF + r * 64 + seg * 8);
            }
            // publish this CTA's slice: bar.sync (intra-CTA HB) + release store
            __syncthreads();
            if (tid == 0) st_release(&flags[jn], (unsigned)(t + 1));
        } else {
            // G0 mode: gates + bias (no x term), gate-major layout
#pragma unroll
            for (int nt = 0; nt < 4; ++nt) {
                float p0 = __shfl_xor_sync(0xffffffffu, acc[nt][0], 1);
                float p1 = __shfl_xor_sync(0xffffffffu, acc[nt][1], 1);
                float p2 = __shfl_xor_sync(0xffffffffu, acc[nt][2], 1);
                float p3 = __shfl_xor_sync(0xffffffffu, acc[nt][3], 1);
                float gi, gf, gg, go;
                if ((l & 1) == 0) { gi = acc[nt][0]; gf = acc[nt][1]; gg = p0; go = p1; }
                else              { gi = p2; gf = p3; gg = acc[nt][2]; go = acc[nt][3]; }
                int gcol = jn * 32 + scolr[nt];
                size_t base = (size_t)erow * G4;
                G0[base + 0 * HID + gcol] = gi + bqr[nt].x;
                G0[base + 1 * HID + gcol] = gf + bqr[nt].y;
                G0[base + 2 * HID + gcol] = gg + bqr[nt].z;
                G0[base + 3 * HID + gcol] = go + bqr[nt].w;
            }
        }
    }
}

// ------------------------------- decoder ------------------------------------
__global__ __launch_bounds__(256)
void decode_kernel(const float* __restrict__ hidden,
                   const float* __restrict__ cell,
                   const float* __restrict__ G0,
                   const float* __restrict__ Wih,
                   const float* __restrict__ Wout,
                   const float* __restrict__ bout,
                   float* __restrict__ out)
{
    const int b = blockIdx.x;
    const int t = threadIdx.x;

    __shared__ float sh[HID];
    __shared__ float red[9];

    float g0[2][4], wv[2][4], cc[2], wo[2];
#pragma unroll
    for (int s = 0; s < 2; ++s) {
        int jj = t + s * 256;
#pragma unroll
        for (int q = 0; q < 4; ++q) {
            g0[s][q] = G0[b * G4 + q * HID + jj];
            wv[s][q] = Wih[q * HID + jj];
        }
        cc[s] = cell[b * HID + jj];
        wo[s] = Wout[jj];
        sh[jj] = hidden[b * HID + jj];
    }
    const float bo = bout[0];
    __syncthreads();

    for (int step = 0; step < DEC_STEPS; ++step) {
        float p = sh[t] * wo[0] + sh[t + 256] * wo[1];
#pragma unroll
        for (int o = 16; o > 0; o >>= 1)
            p += __shfl_down_sync(0xffffffffu, p, o);
        if ((t & 31) == 0) red[t >> 5] = p;
        __syncthreads();
        if (t < 8) {
            float v = red[t];
            v += __shfl_down_sync(0x000000ffu, v, 4);
            v += __shfl_down_sync(0x000000ffu, v, 2);
            v += __shfl_down_sync(0x000000ffu, v, 1);
            if (t == 0) red[8] = v + bo;
        }
        __syncthreads();
        const float ov = red[8];
        if (t == 0) out[b * DEC_STEPS + step] = ov;

        float hn[2];
#pragma unroll
        for (int s = 0; s < 2; ++s) {
            float gi = g0[s][0] + ov * wv[s][0];
            float gf = g0[s][1] + ov * wv[s][1];
            float gg = g0[s][2] + ov * wv[s][2];
            float go = g0[s][3] + ov * wv[s][3];
            float cn = fsigm(gf) * cc[s] + fsigm(gi) * ftanh(gg);
            hn[s] = fsigm(go) * ftanh(cn);
        }
        __syncthreads();
        sh[t]       = hn[0];
        sh[t + 256] = hn[1];
        __syncthreads();
    }
}

// ------------------------------- launch -------------------------------------
extern "C" void kernel_launch(void* const* d_in, const int* in_sizes, int n_in,
                              void* d_out, int out_size)
{
    const float* x     = (const float*)d_in[0];
    const float* W_ih  = (const float*)d_in[1];
    const float* W_hh  = (const float*)d_in[2];
    const float* b_ih  = (const float*)d_in[3];
    const float* b_hh  = (const float*)d_in[4];
    const float* W_out = (const float*)d_in[5];
    const float* b_out = (const float*)d_in[6];
    float* out = (float*)d_out;

    __half *wh, *h0, *h1;
    float *xT, *hf, *c, *G0, *br, *wihr;
    cudaGetSymbolAddress((void**)&wh, g_wh);
    cudaGetSymbolAddress((void**)&h0, g_h0);
    cudaGetSymbolAddress((void**)&h1, g_h1);
    cudaGetSymbolAddress((void**)&xT, g_xT);
    cudaGetSymbolAddress((void**)&hf, g_hf);
    cudaGetSymbolAddress((void**)&c,  g_c);
    cudaGetSymbolAddress((void**)&G0, g_G0);
    cudaGetSymbolAddress((void**)&br, g_br);
    cudaGetSymbolAddress((void**)&wihr, g_wihr);

    cudaFuncSetAttribute(lstm_persist, cudaFuncAttributeMaxDynamicSharedMemorySize, SMEM_TOTAL);

    init_state<<<(BATCH * HID / 2 + 255) / 256, 256>>>((uint32_t*)h0, x, xT);
    wprep<<<(G4 * HID + 255) / 256, 256>>>(W_hh, b_ih, b_hh, W_ih, wh, br, wihr);

    // 128 CTAs, 1/SM (smem-forced) -> all resident; producer-flag dataflow sync
    lstm_persist<<<128, 512, SMEM_TOTAL>>>(wh, br, wihr, xT, h0, h1, hf, c, G0);

    decode_kernel<<<BATCH, 256>>>(hf, c, G0, W_ih, W_out, b_out, out);
}

// round 14
// speedup vs baseline: 2.2766x; 2.2766x over previous
#include <cuda_runtime.h>
#include <cuda_fp16.h>
#include <cstdint>
#include <cstddef>

// Problem constants
#define BATCH 512
#define TSTEPS 256
#define HID 512
#define G4 2048
#define DEC_STEPS 42

// Persistent config: 128 CTAs = 8 m-groups x 16 jn. CTA tile 64(m) x 128(n-reord),
// 512 threads (16 warps = 4m x 4n), warp tile 16x32.
// B slice (128 rows x 512 k fp16) resident in smem; full A staged per step.
#define TM 64
#define TNR 128
#define KC 64
#define NKC 8
#define PITCH 144                          // bytes per smem row (72 fp16)
#define BCHUNK (TNR * PITCH)               // 18432
#define BTOT (NKC * BCHUNK)                // 147456
#define ACHUNK (TM * PITCH)                // 9216
#define AOFF BTOT
#define HOFF (BTOT + NKC * ACHUNK)         // 221184: h staging (4KB)
#define SMEM_TOTAL (HOFF + 4096)           // 225280

// ------------------------- device scratch (no allocs) ----------------------
__device__ __align__(128) __half g_wh[G4 * HID];      // fp16 reordered W_hh
__device__ __align__(128) __half g_h0[BATCH * HID];
__device__ __align__(128) __half g_h1[BATCH * HID];
__device__ __align__(128) float g_xT[TSTEPS * BATCH]; // transposed x
__device__ float g_hf[BATCH * HID];
__device__ float g_c [BATCH * HID];
__device__ float g_G0[BATCH * G4];
__device__ float g_br[G4];
__device__ float g_wihr[G4];
__device__ __align__(128) unsigned g_flags[128];      // per-CTA h-ready flags

// ------------------------------ helpers ------------------------------------
__device__ __forceinline__ uint32_t smem_u32(const void* p) {
    uint32_t a;
    asm("{ .reg .u64 t; cvta.to.shared.u64 t, %1; cvt.u32.u64 %0, t; }" : "=r"(a) : "l"(p));
    return a;
}
__device__ __forceinline__ void cpasync16(uint32_t s, const void* g) {
    asm volatile("cp.async.cg.shared.global [%0], [%1], 16;" :: "r"(s), "l"(g));
}
__device__ __forceinline__ void cpasync_commit() {
    asm volatile("cp.async.commit_group;" ::: "memory");
}
template <int N> __device__ __forceinline__ void cpasync_wait() {
    asm volatile("cp.async.wait_group %0;" :: "n"(N) : "memory");
}
__device__ __forceinline__ void ldsm_x4(uint32_t* r, uint32_t addr) {
    asm volatile("ldmatrix.sync.aligned.m8n8.x4.shared.b16 {%0,%1,%2,%3}, [%4];"
                 : "=r"(r[0]), "=r"(r[1]), "=r"(r[2]), "=r"(r[3]) : "r"(addr));
}
__device__ __forceinline__ void mma16816(float* c, const uint32_t* a, uint32_t b0, uint32_t b1) {
    asm volatile(
        "mma.sync.aligned.m16n8k16.row.col.f32.f16.f16.f32 "
        "{%0,%1,%2,%3}, {%4,%5,%6,%7}, {%8,%9}, {%0,%1,%2,%3};"
        : "+f"(c[0]), "+f"(c[1]), "+f"(c[2]), "+f"(c[3])
        : "r"(a[0]), "r"(a[1]), "r"(a[2]), "r"(a[3]), "r"(b0), "r"(b1));
}
// release/acquire primitives (no full membar)
__device__ __forceinline__ void st_release(unsigned* p, unsigned v) {
    asm volatile("st.release.gpu.global.u32 [%0], %1;" :: "l"(p), "r"(v) : "memory");
}
__device__ __forceinline__ unsigned ld_acquire(const unsigned* p) {
    unsigned v;
    asm volatile("ld.acquire.gpu.global.u32 %0, [%1];" : "=r"(v) : "l"(p) : "memory");
    return v;
}
// fast transcendental (MUFU.EX2 based); per-op rel err ~1e-6
__device__ __forceinline__ float fsigm(float v) {
    return __fdividef(1.0f, 1.0f + __expf(-v));
}
__device__ __forceinline__ float ftanh(float v) {
    v = fminf(fmaxf(v, -15.0f), 15.0f);
    float e = __expf(2.0f * v);
    return __fdividef(e - 1.0f, e + 1.0f);
}

// -------------------------- init / prep kernels -----------------------------
__global__ void init_state(uint32_t* h0, const float* __restrict__ x,
                           float* __restrict__ xT) {
    int i = blockIdx.x * 256 + threadIdx.x;
    if (i < BATCH * HID / 2) h0[i] = 0u;
    if (i < TSTEPS * BATCH) {
        int t = i >> 9, b = i & 511;         // xT[t*512+b] = x[b*256+t]
        xT[i] = x[b * TSTEPS + t];
    }
    if (i < 128) g_flags[i] = 0u;
}

// Convert W_hh to fp16 with per-column gate interleave:
//   old row r = q*512 + col, col = jn*32 + s  ->  new row = jn*128 + s*4 + q
__global__ void wprep(const float* __restrict__ Whh,
                      const float* __restrict__ b_ih, const float* __restrict__ b_hh,
                      const float* __restrict__ Wih,
                      __half* __restrict__ wh,
                      float* __restrict__ br, float* __restrict__ wihr)
{
    int i = blockIdx.x * 256 + threadIdx.x;
    if (i >= G4 * HID) return;
    int old_r = i / HID;
    int k = i - old_r * HID;
    int q = old_r >> 9;
    int col = old_r & 511;
    int jn = col >> 5;
    int s = col & 31;
    int new_r = jn * 128 + s * 4 + q;
    wh[new_r * HID + k] = __float2half(Whh[i]);
    if (k == 0) {
        br[new_r] = b_ih[old_r] + b_hh[old_r];
        wihr[new_r] = Wih[old_r];
    }
}

// ----------------------- persistent encoder kernel --------------------------
__global__ __launch_bounds__(512, 1)
void lstm_persist(const __half* __restrict__ wh,
                  const float* __restrict__ br, const float* __restrict__ wihr,
                  const float* __restrict__ xT,
                  __half* __restrict__ h0g, __half* __restrict__ h1g,
                  float* __restrict__ hf, float* __restrict__ cg,
                  float* __restrict__ G0)
{
    extern __shared__ __align__(16) char smem[];
    const uint32_t sb = smem_u32(smem);
    const int tid = threadIdx.x;
    const int wid = tid >> 5;
    const int l = tid & 31;
    const int wm = wid & 3;               // 0..3: 16-row m tile
    const int wn = wid >> 2;              // 0..3: 32-col n tile
    const int jn = blockIdx.x & 15;       // 0..15 (32 logical cols each)
    const int mg = blockIdx.x >> 4;       // 0..7  m-group
    const int m0 = mg * TM;
    const int n0 = jn * TNR;              // reordered W row base

    // ---- load resident B slice (128 rows x 512 k), chunked by KC ----
#pragma unroll
    for (int it = 0; it < 16; ++it) {
        int slot = tid + it * 512;        // 0..8191
        int seg = slot & 7;
        int r = (slot >> 3) & 127;
        int kc = slot >> 10;
        cpasync16(sb + (uint32_t)(kc * BCHUNK + r * PITCH + seg * 16),
                  (const char*)wh + ((size_t)(n0 + r) * HID + kc * KC) * 2 + seg * 16);
    }
    cpasync_commit();
    cpasync_wait<0>();
    __syncthreads();

    // per-lane ldmatrix byte offsets
    const uint32_t aoff = (uint32_t)((l & 15) * PITCH + (l >> 4) * 16);
    const uint32_t boff = (uint32_t)(((l & 7) + ((l >> 4) << 3)) * PITCH + ((l >> 3) & 1) * 16);

    // epilogue cell mapping (fixed across steps): c in registers
    const int erl = wm * 16 + (l >> 2) + ((l & 1) ? 8 : 0);   // local row 0..63
    const int erow = m0 + erl;
    float creg[4] = {0.f, 0.f, 0.f, 0.f};

    // preload per-thread bias / W_ih constants (fixed across steps)
    float4 bqr[4], wqr[4];
    int scolr[4];
#pragma unroll
    for (int nt = 0; nt < 4; ++nt) {
        int scol = wn * 8 + nt * 2 + ((l & 3) >> 1);
        scolr[nt] = scol;
        bqr[nt] = *reinterpret_cast<const float4*>(&br[n0 + scol * 4]);
        wqr[nt] = *reinterpret_cast<const float4*>(&wihr[n0 + scol * 4]);
    }

    unsigned* flags = &g_flags[mg * 16];
    __half* shh = reinterpret_cast<__half*>(smem + HOFF);

#pragma unroll 1
    for (int t = 0; t <= TSTEPS; ++t) {
        const __half* hin = (t & 1) ? h1g : h0g;
        __half* hout      = (t & 1) ? h0g : h1g;

        // ---- stage full A (64 x 512) in two halves, gated by producer flags.
        // Half h needs chunks 4h..4h+3, produced by CTAs jn = 8h..8h+7.
        // ONLY warp 0 lanes 0..7 poll (128 CTAs x 8 = 1K pollers chip-wide,
        // 16 pollers per flag word -- same per-word rate as the R12 counter).
        // All warps gate their cp.async issue on the poll via __syncthreads.
#pragma unroll
        for (int half = 0; half < 2; ++half) {
            if (t > 0) {
                if (wid == 0 && l < 8) {
                    const unsigned* f = &flags[half * 8 + l];
                    while (ld_acquire(f) < (unsigned)t) { }
                }
                __syncthreads();
            }
#pragma unroll
            for (int it = 0; it < 4; ++it) {
                int slot = tid + it * 512;           // 0..2047
                int seg = slot & 7;
                int r = (slot >> 3) & 63;
                int kc = half * 4 + it;
                cpasync16(sb + AOFF + (uint32_t)(kc * ACHUNK + r * PITCH + seg * 16),
                          (const char*)hin + ((size_t)(m0 + r) * HID + kc * KC) * 2 + seg * 16);
            }
            cpasync_commit();
        }

        float acc[4][4];
#pragma unroll
        for (int nt = 0; nt < 4; ++nt)
#pragma unroll
            for (int v = 0; v < 4; ++v) acc[nt][v] = 0.0f;

        // ---- MMA: half 0 while half 1 lands, then half 1 ----
#pragma unroll
        for (int half = 0; half < 2; ++half) {
            if (half == 0) cpasync_wait<1>(); else cpasync_wait<0>();
            __syncthreads();
#pragma unroll
            for (int kci = 0; kci < 4; ++kci) {
                int kc = half * 4 + kci;
                const uint32_t stA = sb + AOFF + (uint32_t)(kc * ACHUNK + wm * 16 * PITCH);
                const uint32_t stB = sb + (uint32_t)(kc * BCHUNK + wn * 32 * PITCH);
#pragma unroll
                for (int ks = 0; ks < 4; ++ks) {
                    const uint32_t ka = (uint32_t)(ks * 32);   // 16 fp16 = 32B
                    uint32_t ar[4], b0r[4], b1r[4];
                    ldsm_x4(ar, stA + ka + aoff);
                    ldsm_x4(b0r, stB + ka + boff);
                    ldsm_x4(b1r, stB + (uint32_t)(16 * PITCH) + ka + boff);
                    mma16816(acc[0], ar, b0r[0], b0r[1]);
                    mma16816(acc[1], ar, b0r[2], b0r[3]);
                    mma16816(acc[2], ar, b1r[0], b1r[1]);
                    mma16816(acc[3], ar, b1r[2], b1r[3]);
                }
            }
        }

        // ---------------- register epilogue (shfl gate gather) ---------------
        // acc[nt] col n_local = wn*32 + nt*8 + (l&3)*2 (+1) = s*4 + q.
        // Lanes l, l^1 hold (i,f)/(g,o) of the same logical column.
        if (t < TSTEPS) {
            const float xv = xT[t * BATCH + erow];
#pragma unroll
            for (int nt = 0; nt < 4; ++nt) {
                float p0 = __shfl_xor_sync(0xffffffffu, acc[nt][0], 1);
                float p1 = __shfl_xor_sync(0xffffffffu, acc[nt][1], 1);
                float p2 = __shfl_xor_sync(0xffffffffu, acc[nt][2], 1);
                float p3 = __shfl_xor_sync(0xffffffffu, acc[nt][3], 1);
                float gi, gf, gg, go;
                if ((l & 1) == 0) { gi = acc[nt][0]; gf = acc[nt][1]; gg = p0; go = p1; }
                else              { gi = p2; gf = p3; gg = acc[nt][2]; go = acc[nt][3]; }
                gi += bqr[nt].x + xv * wqr[nt].x;
                gf += bqr[nt].y + xv * wqr[nt].y;
                gg += bqr[nt].z + xv * wqr[nt].z;
                go += bqr[nt].w + xv * wqr[nt].w;
                float cn = fsigm(gf) * creg[nt] + fsigm(gi) * ftanh(gg);
                creg[nt] = cn;
                float hv = fsigm(go) * ftanh(cn);
                shh[erl * 32 + scolr[nt]] = __float2half(hv);
                if (t == TSTEPS - 1) {
                    int idx = erow * HID + jn * 32 + scolr[nt];
                    hf[idx] = hv; cg[idx] = cn;
                }
            }
            __syncthreads();
            // coalesced copy-out: 64 rows x 32 halfs (64B/row), 512 x 8B STG
            {
                int r = tid >> 3, seg = tid & 7;
                *reinterpret_cast<uint64_t*>(&hout[(m0 + r) * HID + jn * 32 + seg * 4]) =
                    *reinterpret_cast<const uint64_t*>(smem + HOFF + r * 64 + seg * 8);
            }
            // publish this CTA's slice: bar.sync (intra-CTA HB) + release store
            __syncthreads();
            if (tid == 0) st_release(&flags[jn], (unsigned)(t + 1));
        } else {
            // G0 mode: gates + bias (no x term), gate-major layout
#pragma unroll
            for (int nt = 0; nt < 4; ++nt) {
                float p0 = __shfl_xor_sync(0xffffffffu, acc[nt][0], 1);
                float p1 = __shfl_xor_sync(0xffffffffu, acc[nt][1], 1);
                float p2 = __shfl_xor_sync(0xffffffffu, acc[nt][2], 1);
                float p3 = __shfl_xor_sync(0xffffffffu, acc[nt][3], 1);
                float gi, gf, gg, go;
                if ((l & 1) == 0) { gi = acc[nt][0]; gf = acc[nt][1]; gg = p0; go = p1; }
                else              { gi = p2; gf = p3; gg = acc[nt][2]; go = acc[nt][3]; }
                int gcol = jn * 32 + scolr[nt];
                size_t base = (size_t)erow * G4;
                G0[base + 0 * HID + gcol] = gi + bqr[nt].x;
                G0[base + 1 * HID + gcol] = gf + bqr[nt].y;
                G0[base + 2 * HID + gcol] = gg + bqr[nt].z;
                G0[base + 3 * HID + gcol] = go + bqr[nt].w;
            }
        }
    }
}

// ------------------------------- decoder ------------------------------------
__global__ __launch_bounds__(256)
void decode_kernel(const float* __restrict__ hidden,
                   const float* __restrict__ cell,
                   const float* __restrict__ G0,
                   const float* __restrict__ Wih,
                   const float* __restrict__ Wout,
                   const float* __restrict__ bout,
                   float* __restrict__ out)
{
    const int b = blockIdx.x;
    const int t = threadIdx.x;

    __shared__ float sh[HID];
    __shared__ float red[9];

    float g0[2][4], wv[2][4], cc[2], wo[2];
#pragma unroll
    for (int s = 0; s < 2; ++s) {
        int jj = t + s * 256;
#pragma unroll
        for (int q = 0; q < 4; ++q) {
            g0[s][q] = G0[b * G4 + q * HID + jj];
            wv[s][q] = Wih[q * HID + jj];
        }
        cc[s] = cell[b * HID + jj];
        wo[s] = Wout[jj];
        sh[jj] = hidden[b * HID + jj];
    }
    const float bo = bout[0];
    __syncthreads();

    for (int step = 0; step < DEC_STEPS; ++step) {
        float p = sh[t] * wo[0] + sh[t + 256] * wo[1];
#pragma unroll
        for (int o = 16; o > 0; o >>= 1)
            p += __shfl_down_sync(0xffffffffu, p, o);
        if ((t & 31) == 0) red[t >> 5] = p;
        __syncthreads();
        if (t < 8) {
            float v = red[t];
            v += __shfl_down_sync(0x000000ffu, v, 4);
            v += __shfl_down_sync(0x000000ffu, v, 2);
            v += __shfl_down_sync(0x000000ffu, v, 1);
            if (t == 0) red[8] = v + bo;
        }
        __syncthreads();
        const float ov = red[8];
        if (t == 0) out[b * DEC_STEPS + step] = ov;

        float hn[2];
#pragma unroll
        for (int s = 0; s < 2; ++s) {
            float gi = g0[s][0] + ov * wv[s][0];
            float gf = g0[s][1] + ov * wv[s][1];
            float gg = g0[s][2] + ov * wv[s][2];
            float go = g0[s][3] + ov * wv[s][3];
            float cn = fsigm(gf) * cc[s] + fsigm(gi) * ftanh(gg);
            hn[s] = fsigm(go) * ftanh(cn);
        }
        __syncthreads();
        sh[t]       = hn[0];
        sh[t + 256] = hn[1];
        __syncthreads();
    }
}

// ------------------------------- launch -------------------------------------
extern "C" void kernel_launch(void* const* d_in, const int* in_sizes, int n_in,
                              void* d_out, int out_size)
{
    const float* x     = (const float*)d_in[0];
    const float* W_ih  = (const float*)d_in[1];
    const float* W_hh  = (const float*)d_in[2];
    const float* b_ih  = (const float*)d_in[3];
    const float* b_hh  = (const float*)d_in[4];
    const float* W_out = (const float*)d_in[5];
    const float* b_out = (const float*)d_in[6];
    float* out = (float*)d_out;

    __half *wh, *h0, *h1;
    float *xT, *hf, *c, *G0, *br, *wihr;
    cudaGetSymbolAddress((void**)&wh, g_wh);
    cudaGetSymbolAddress((void**)&h0, g_h0);
    cudaGetSymbolAddress((void**)&h1, g_h1);
    cudaGetSymbolAddress((void**)&xT, g_xT);
    cudaGetSymbolAddress((void**)&hf, g_hf);
    cudaGetSymbolAddress((void**)&c,  g_c);
    cudaGetSymbolAddress((void**)&G0, g_G0);
    cudaGetSymbolAddress((void**)&br, g_br);
    cudaGetSymbolAddress((void**)&wihr, g_wihr);

    cudaFuncSetAttribute(lstm_persist, cudaFuncAttributeMaxDynamicSharedMemorySize, SMEM_TOTAL);

    init_state<<<(BATCH * HID / 2 + 255) / 256, 256>>>((uint32_t*)h0, x, xT);
    wprep<<<(G4 * HID + 255) / 256, 256>>>(W_hh, b_ih, b_hh, W_ih, wh, br, wihr);

    // 128 CTAs, 1/SM (smem-forced) -> all resident; producer-flag dataflow sync
    lstm_persist<<<128, 512, SMEM_TOTAL>>>(wh, br, wihr, xT, h0, h1, hf, c, G0);

    decode_kernel<<<BATCH, 256>>>(hf, c, G0, W_ih, W_out, b_out, out);
}

// round 15
// speedup vs baseline: 2.6138x; 1.1482x over previous
#include <cuda_runtime.h>
#include <cuda_fp16.h>
#include <cstdint>
#include <cstddef>

// Problem constants
#define BATCH 512
#define TSTEPS 256
#define HID 512
#define G4 2048
#define DEC_STEPS 42

// Persistent config: 256 CTAs = 8 m-groups x 32 jn, 2 CTAs/SM.
// CTA tile 64(m) x 64(n-reord), 256 threads (8 warps = 4m x 2n), warp tile 16x32.
// B slice (64 rows x 512 k fp16) resident in smem; A 2-stage KC=128 chunks.
#define TM 64
#define TNR 64
#define PITCHB 144                         // B smem row pitch (72 fp16)
#define BCHUNK (TNR * PITCHB)              // 9216 per 64-k chunk
#define BTOT (8 * BCHUNK)                  // 73728
#define KCA 128                            // A k-chunk
#define NAC 4                              // 512/128
#define PITCHA 272                         // A row pitch (256B data + 16 pad)
#define ACH (TM * PITCHA)                  // 17408
#define AOFF BTOT
#define HOFF (BTOT + 2 * ACH)              // 108544
#define SMEM_TOTAL (HOFF + 2048)           // 110592 (x2 = 221184 < 228K)

// ------------------------- device scratch (no allocs) ----------------------
__device__ __align__(128) __half g_wh[G4 * HID];      // fp16 reordered W_hh
__device__ __align__(128) __half g_h0[BATCH * HID];
__device__ __align__(128) __half g_h1[BATCH * HID];
__device__ __align__(128) float g_xT[TSTEPS * BATCH]; // transposed x
__device__ float g_hf[BATCH * HID];
__device__ float g_c [BATCH * HID];
__device__ float g_G0[BATCH * G4];
__device__ float g_br[G4];
__device__ float g_wihr[G4];
__device__ unsigned g_cnt[8];                         // per-m-group barrier counters

// ------------------------------ helpers ------------------------------------
__device__ __forceinline__ uint32_t smem_u32(const void* p) {
    uint32_t a;
    asm("{ .reg .u64 t; cvta.to.shared.u64 t, %1; cvt.u32.u64 %0, t; }" : "=r"(a) : "l"(p));
    return a;
}
__device__ __forceinline__ void cpasync16(uint32_t s, const void* g) {
    asm volatile("cp.async.cg.shared.global [%0], [%1], 16;" :: "r"(s), "l"(g));
}
__device__ __forceinline__ void cpasync_commit() {
    asm volatile("cp.async.commit_group;" ::: "memory");
}
template <int N> __device__ __forceinline__ void cpasync_wait() {
    asm volatile("cp.async.wait_group %0;" :: "n"(N) : "memory");
}
__device__ __forceinline__ void ldsm_x4(uint32_t* r, uint32_t addr) {
    asm volatile("ldmatrix.sync.aligned.m8n8.x4.shared.b16 {%0,%1,%2,%3}, [%4];"
                 : "=r"(r[0]), "=r"(r[1]), "=r"(r[2]), "=r"(r[3]) : "r"(addr));
}
__device__ __forceinline__ void mma16816(float* c, const uint32_t* a, uint32_t b0, uint32_t b1) {
    asm volatile(
        "mma.sync.aligned.m16n8k16.row.col.f32.f16.f16.f32 "
        "{%0,%1,%2,%3}, {%4,%5,%6,%7}, {%8,%9}, {%0,%1,%2,%3};"
        : "+f"(c[0]), "+f"(c[1]), "+f"(c[2]), "+f"(c[3])
        : "r"(a[0]), "r"(a[1]), "r"(a[2]), "r"(a[3]), "r"(b0), "r"(b1));
}
// release/acquire primitives (no full membar)
__device__ __forceinline__ void red_release_add(unsigned* p, unsigned v) {
    asm volatile("red.release.gpu.global.add.u32 [%0], %1;" :: "l"(p), "r"(v) : "memory");
}
__device__ __forceinline__ unsigned ld_acquire(const unsigned* p) {
    unsigned v;
    asm volatile("ld.acquire.gpu.global.u32 %0, [%1];" : "=r"(v) : "l"(p) : "memory");
    return v;
}
// fast transcendental (MUFU.EX2 based); per-op rel err ~1e-6
__device__ __forceinline__ float fsigm(float v) {
    return __fdividef(1.0f, 1.0f + __expf(-v));
}
__device__ __forceinline__ float ftanh(float v) {
    v = fminf(fmaxf(v, -15.0f), 15.0f);
    float e = __expf(2.0f * v);
    return __fdividef(e - 1.0f, e + 1.0f);
}

// -------------------------- init / prep kernels -----------------------------
__global__ void init_state(uint32_t* h0, const float* __restrict__ x,
                           float* __restrict__ xT) {
    int i = blockIdx.x * 256 + threadIdx.x;
    if (i < BATCH * HID / 2) h0[i] = 0u;
    if (i < TSTEPS * BATCH) {
        int t = i >> 9, b = i & 511;         // xT[t*512+b] = x[b*256+t]
        xT[i] = x[b * TSTEPS + t];
    }
    if (i < 8) g_cnt[i] = 0u;
}

// Convert W_hh to fp16 with per-column gate interleave:
//   old row r = q*512 + col, col = jn*16 + s  ->  new row = jn*64 + s*4 + q
__global__ void wprep(const float* __restrict__ Whh,
                      const float* __restrict__ b_ih, const float* __restrict__ b_hh,
                      const float* __restrict__ Wih,
                      __half* __restrict__ wh,
                      float* __restrict__ br, float* __restrict__ wihr)
{
    int i = blockIdx.x * 256 + threadIdx.x;
    if (i >= G4 * HID) return;
    int old_r = i / HID;
    int k = i - old_r * HID;
    int q = old_r >> 9;
    int col = old_r & 511;
    int jn = col >> 4;
    int s = col & 15;
    int new_r = jn * 64 + s * 4 + q;
    wh[new_r * HID + k] = __float2half(Whh[i]);
    if (k == 0) {
        br[new_r] = b_ih[old_r] + b_hh[old_r];
        wihr[new_r] = Wih[old_r];
    }
}

// ----------------------- persistent encoder kernel --------------------------
__global__ __launch_bounds__(256, 2)
void lstm_persist(const __half* __restrict__ wh,
                  const float* __restrict__ br, const float* __restrict__ wihr,
                  const float* __restrict__ xT,
                  __half* __restrict__ h0g, __half* __restrict__ h1g,
                  float* __restrict__ hf, float* __restrict__ cg,
                  float* __restrict__ G0)
{
    extern __shared__ __align__(16) char smem[];
    const uint32_t sb = smem_u32(smem);
    const int tid = threadIdx.x;
    const int wid = tid >> 5;
    const int l = tid & 31;
    const int wm = wid & 3;               // 0..3: 16-row m tile
    const int wn = wid >> 2;              // 0..1: 32-col n tile
    const int jn = blockIdx.x & 31;       // 0..31 (16 logical cols each)
    const int mg = blockIdx.x >> 5;       // 0..7  m-group
    const int m0 = mg * TM;
    const int n0 = jn * TNR;              // reordered W row base

    // ---- load resident B slice (64 rows x 512 k), 8 chunks of 64 k ----
#pragma unroll
    for (int it = 0; it < 16; ++it) {
        int slot = tid + it * 256;        // 0..4095
        int seg = slot & 7;
        int r = (slot >> 3) & 63;
        int kc = slot >> 9;
        cpasync16(sb + (uint32_t)(kc * BCHUNK + r * PITCHB + seg * 16),
                  (const char*)wh + ((size_t)(n0 + r) * HID + kc * 64) * 2 + seg * 16);
    }
    cpasync_commit();
    cpasync_wait<0>();
    __syncthreads();

    // per-lane ldmatrix byte offsets
    const uint32_t aoff = (uint32_t)((l & 15) * PITCHA + (l >> 4) * 16);
    const uint32_t boff = (uint32_t)(((l & 7) + ((l >> 4) << 3)) * PITCHB + ((l >> 3) & 1) * 16);

    // epilogue cell mapping (fixed across steps): c in registers
    const int erl = wm * 16 + (l >> 2) + ((l & 1) ? 8 : 0);   // local row 0..63
    const int erow = m0 + erl;
    float creg[4] = {0.f, 0.f, 0.f, 0.f};

    // preload per-thread bias / W_ih constants (fixed across steps)
    float4 bqr[4], wqr[4];
    int scolr[4];
#pragma unroll
    for (int nt = 0; nt < 4; ++nt) {
        int scol = wn * 8 + nt * 2 + ((l & 3) >> 1);          // 0..15
        scolr[nt] = scol;
        bqr[nt] = *reinterpret_cast<const float4*>(&br[n0 + scol * 4]);
        wqr[nt] = *reinterpret_cast<const float4*>(&wihr[n0 + scol * 4]);
    }

    unsigned* cnt = &g_cnt[mg];
    __half* shh = reinterpret_cast<__half*>(smem + HOFF);

#pragma unroll 1
    for (int t = 0; t <= TSTEPS; ++t) {
        const __half* hin = (t & 1) ? h1g : h0g;
        __half* hout      = (t & 1) ? h0g : h1g;

        // A chunk loader: 64 rows x 256B, 1024 x 16B transfers (4 per thread)
        auto loadA = [&](int stage, int ac) {
            uint32_t dst = sb + AOFF + (uint32_t)(stage * ACH);
#pragma unroll
            for (int it = 0; it < 4; ++it) {
                int slot = tid + it * 256;       // 0..1023
                int seg = slot & 15;
                int r = slot >> 4;
                cpasync16(dst + (uint32_t)(r * PITCHA + seg * 16),
                          (const char*)hin + ((size_t)(m0 + r) * HID + ac * KCA) * 2 + seg * 16);
            }
            cpasync_commit();
        };

        float acc[4][4];
#pragma unroll
        for (int nt = 0; nt < 4; ++nt)
#pragma unroll
            for (int v = 0; v < 4; ++v) acc[nt][v] = 0.0f;

        loadA(0, 0);

        // ---- MMA over 4 A-chunks, 2-stage pipeline (1 wait + 1 sync each) --
#pragma unroll 1
        for (int ac = 0; ac < NAC; ++ac) {
            cpasync_wait<0>();                  // chunk ac resident
            __syncthreads();                    // + all warps past MMA(ac-1)
            if (ac + 1 < NAC) loadA((ac + 1) & 1, ac + 1);

            const uint32_t stA = sb + AOFF + (uint32_t)(((ac) & 1) * ACH + wm * 16 * PITCHA);
#pragma unroll
            for (int ks = 0; ks < 8; ++ks) {
                const uint32_t stB = sb + (uint32_t)((ac * 2 + (ks >> 2)) * BCHUNK + wn * 32 * PITCHB);
                const uint32_t ka = (uint32_t)((ks & 3) * 32);   // 16 fp16 = 32B
                uint32_t ar[4], b0r[4], b1r[4];
                ldsm_x4(ar, stA + (uint32_t)(ks * 32) + aoff);
                ldsm_x4(b0r, stB + ka + boff);
                ldsm_x4(b1r, stB + (uint32_t)(16 * PITCHB) + ka + boff);
                mma16816(acc[0], ar, b0r[0], b0r[1]);
                mma16816(acc[1], ar, b0r[2], b0r[3]);
                mma16816(acc[2], ar, b1r[0], b1r[1]);
                mma16816(acc[3], ar, b1r[2], b1r[3]);
            }
        }

        // ---------------- register epilogue (shfl gate gather) ---------------
        // acc[nt] col n_local = wn*32 + nt*8 + (l&3)*2 (+1) = s*4 + q.
        // Lanes l, l^1 hold (i,f)/(g,o) of the same logical column.
        if (t < TSTEPS) {
            const float xv = xT[t * BATCH + erow];
#pragma unroll
            for (int nt = 0; nt < 4; ++nt) {
                float p0 = __shfl_xor_sync(0xffffffffu, acc[nt][0], 1);
                float p1 = __shfl_xor_sync(0xffffffffu, acc[nt][1], 1);
                float p2 = __shfl_xor_sync(0xffffffffu, acc[nt][2], 1);
                float p3 = __shfl_xor_sync(0xffffffffu, acc[nt][3], 1);
                float gi, gf, gg, go;
                if ((l & 1) == 0) { gi = acc[nt][0]; gf = acc[nt][1]; gg = p0; go = p1; }
                else              { gi = p2; gf = p3; gg = acc[nt][2]; go = acc[nt][3]; }
                gi += bqr[nt].x + xv * wqr[nt].x;
                gf += bqr[nt].y + xv * wqr[nt].y;
                gg += bqr[nt].z + xv * wqr[nt].z;
                go += bqr[nt].w + xv * wqr[nt].w;
                float cn = fsigm(gf) * creg[nt] + fsigm(gi) * ftanh(gg);
                creg[nt] = cn;
                float hv = fsigm(go) * ftanh(cn);
                shh[erl * 16 + scolr[nt]] = __float2half(hv);
                if (t == TSTEPS - 1) {
                    int idx = erow * HID + jn * 16 + scolr[nt];
                    hf[idx] = hv; cg[idx] = cn;
                }
            }
            __syncthreads();
            // coalesced copy-out: 64 rows x 16 halfs (32B/row), 256 x 8B STG
            {
                int r = tid >> 2, seg = tid & 3;
                *reinterpret_cast<uint64_t*>(&hout[(m0 + r) * HID + jn * 16 + seg * 4]) =
                    *reinterpret_cast<const uint64_t*>(smem + HOFF + r * 32 + seg * 8);
            }
            // ---- group barrier (32 CTAs sharing m-group) ----
            __syncthreads();
            if (tid == 0) {
                red_release_add(cnt, 1u);
                unsigned target = 32u * (unsigned)(t + 1);
                while (ld_acquire(cnt) < target) { }
            }
            __syncthreads();
        } else {
            // G0 mode: gates + bias (no x term), gate-major layout
#pragma unroll
            for (int nt = 0; nt < 4; ++nt) {
                float p0 = __shfl_xor_sync(0xffffffffu, acc[nt][0], 1);
                float p1 = __shfl_xor_sync(0xffffffffu, acc[nt][1], 1);
                float p2 = __shfl_xor_sync(0xffffffffu, acc[nt][2], 1);
                float p3 = __shfl_xor_sync(0xffffffffu, acc[nt][3], 1);
                float gi, gf, gg, go;
                if ((l & 1) == 0) { gi = acc[nt][0]; gf = acc[nt][1]; gg = p0; go = p1; }
                else              { gi = p2; gf = p3; gg = acc[nt][2]; go = acc[nt][3]; }
                int gcol = jn * 16 + scolr[nt];
                size_t base = (size_t)erow * G4;
                G0[base + 0 * HID + gcol] = gi + bqr[nt].x;
                G0[base + 1 * HID + gcol] = gf + bqr[nt].y;
                G0[base + 2 * HID + gcol] = gg + bqr[nt].z;
                G0[base + 3 * HID + gcol] = go + bqr[nt].w;
            }
        }
    }
}

// ------------------------------- decoder ------------------------------------
__global__ __launch_bounds__(256)
void decode_kernel(const float* __restrict__ hidden,
                   const float* __restrict__ cell,
                   const float* __restrict__ G0,
                   const float* __restrict__ Wih,
                   const float* __restrict__ Wout,
                   const float* __restrict__ bout,
                   float* __restrict__ out)
{
    const int b = blockIdx.x;
    const int t = threadIdx.x;

    __shared__ float sh[HID];
    __shared__ float red[9];

    float g0[2][4], wv[2][4], cc[2], wo[2];
#pragma unroll
    for (int s = 0; s < 2; ++s) {
        int jj = t + s * 256;
#pragma unroll
        for (int q = 0; q < 4; ++q) {
            g0[s][q] = G0[b * G4 + q * HID + jj];
            wv[s][q] = Wih[q * HID + jj];
        }
        cc[s] = cell[b * HID + jj];
        wo[s] = Wout[jj];
        sh[jj] = hidden[b * HID + jj];
    }
    const float bo = bout[0];
    __syncthreads();

    for (int step = 0; step < DEC_STEPS; ++step) {
        float p = sh[t] * wo[0] + sh[t + 256] * wo[1];
#pragma unroll
        for (int o = 16; o > 0; o >>= 1)
            p += __shfl_down_sync(0xffffffffu, p, o);
        if ((t & 31) == 0) red[t >> 5] = p;
        __syncthreads();
        if (t < 8) {
            float v = red[t];
            v += __shfl_down_sync(0x000000ffu, v, 4);
            v += __shfl_down_sync(0x000000ffu, v, 2);
            v += __shfl_down_sync(0x000000ffu, v, 1);
            if (t == 0) red[8] = v + bo;
        }
        __syncthreads();
        const float ov = red[8];
        if (t == 0) out[b * DEC_STEPS + step] = ov;

        float hn[2];
#pragma unroll
        for (int s = 0; s < 2; ++s) {
            float gi = g0[s][0] + ov * wv[s][0];
            float gf = g0[s][1] + ov * wv[s][1];
            float gg = g0[s][2] + ov * wv[s][2];
            float go = g0[s][3] + ov * wv[s][3];
            float cn = fsigm(gf) * cc[s] + fsigm(gi) * ftanh(gg);
            hn[s] = fsigm(go) * ftanh(cn);
        }
        __syncthreads();
        sh[t]       = hn[0];
        sh[t + 256] = hn[1];
        __syncthreads();
    }
}

// ------------------------------- launch -------------------------------------
extern "C" void kernel_launch(void* const* d_in, const int* in_sizes, int n_in,
                              void* d_out, int out_size)
{
    const float* x     = (const float*)d_in[0];
    const float* W_ih  = (const float*)d_in[1];
    const float* W_hh  = (const float*)d_in[2];
    const float* b_ih  = (const float*)d_in[3];
    const float* b_hh  = (const float*)d_in[4];
    const float* W_out = (const float*)d_in[5];
    const float* b_out = (const float*)d_in[6];
    float* out = (float*)d_out;

    __half *wh, *h0, *h1;
    float *xT, *hf, *c, *G0, *br, *wihr;
    cudaGetSymbolAddress((void**)&wh, g_wh);
    cudaGetSymbolAddress((void**)&h0, g_h0);
    cudaGetSymbolAddress((void**)&h1, g_h1);
    cudaGetSymbolAddress((void**)&xT, g_xT);
    cudaGetSymbolAddress((void**)&hf, g_hf);
    cudaGetSymbolAddress((void**)&c,  g_c);
    cudaGetSymbolAddress((void**)&G0, g_G0);
    cudaGetSymbolAddress((void**)&br, g_br);
    cudaGetSymbolAddress((void**)&wihr, g_wihr);

    cudaFuncSetAttribute(lstm_persist, cudaFuncAttributeMaxDynamicSharedMemorySize, SMEM_TOTAL);

    init_state<<<(BATCH * HID / 2 + 255) / 256, 256>>>((uint32_t*)h0, x, xT);
    wprep<<<(G4 * HID + 255) / 256, 256>>>(W_hh, b_ih, b_hh, W_ih, wh, br, wihr);

    // 256 CTAs, 2/SM (smem-limited), all resident; 8 counter barrier groups
    lstm_persist<<<256, 256, SMEM_TOTAL>>>(wh, br, wihr, xT, h0, h1, hf, c, G0);

    decode_kernel<<<BATCH, 256>>>(hf, c, G0, W_ih, W_out, b_out, out);
}

// round 17
// speedup vs baseline: 2.7133x; 1.0381x over previous
#include <cuda_runtime.h>
#include <cuda_fp16.h>
#include <cstdint>
#include <cstddef>

// Problem constants
#define BATCH 512
#define TSTEPS 256
#define HID 512
#define G4 2048
#define DEC_STEPS 42

// Persistent config: 128 CTAs = 4 m-groups x 32 jn, 1 CTA/SM.
// CTA tile 128(m) x 64(n-reord), 256 threads (8 warps = 4m x 2n), warp tile 32x32.
// B slice (64 rows x 512 k) resident; full A (128 x 512) staged in two halves.
#define TM 128
#define TNR 64
#define PITCH 144                          // smem row pitch (72 fp16)
#define BCHUNK (TNR * PITCH)               // 9216 per 64-k chunk
#define BTOT (8 * BCHUNK)                  // 73728
#define ACHUNK (TM * PITCH)                // 18432 per 64-k chunk
#define AOFF BTOT
#define HOFF (BTOT + 8 * ACHUNK)           // 221184
#define SMEM_TOTAL (HOFF + 4096)           // 225280

// ------------------------- device scratch (no allocs) ----------------------
__device__ __align__(128) __half g_wh[G4 * HID];      // fp16 reordered W_hh
__device__ __align__(128) __half g_h0[BATCH * HID];
__device__ __align__(128) __half g_h1[BATCH * HID];
__device__ __align__(128) float g_xT[TSTEPS * BATCH]; // transposed x
__device__ float g_hf[BATCH * HID];
__device__ float g_c [BATCH * HID];
__device__ float g_G0[BATCH * G4];
__device__ float g_br[G4];
__device__ float g_wihr[G4];
__device__ unsigned g_cnt[4];                         // per-m-group barrier counters

// ------------------------------ helpers ------------------------------------
__device__ __forceinline__ uint32_t smem_u32(const void* p) {
    uint32_t a;
    asm("{ .reg .u64 t; cvta.to.shared.u64 t, %1; cvt.u32.u64 %0, t; }" : "=r"(a) : "l"(p));
    return a;
}
__device__ __forceinline__ void cpasync16(uint32_t s, const void* g) {
    asm volatile("cp.async.cg.shared.global [%0], [%1], 16;" :: "r"(s), "l"(g));
}
__device__ __forceinline__ void cpasync_commit() {
    asm volatile("cp.async.commit_group;" ::: "memory");
}
template <int N> __device__ __forceinline__ void cpasync_wait() {
    asm volatile("cp.async.wait_group %0;" :: "n"(N) : "memory");
}
__device__ __forceinline__ void ldsm_x4(uint32_t* r, uint32_t addr) {
    asm volatile("ldmatrix.sync.aligned.m8n8.x4.shared.b16 {%0,%1,%2,%3}, [%4];"
                 : "=r"(r[0]), "=r"(r[1]), "=r"(r[2]), "=r"(r[3]) : "r"(addr));
}
__device__ __forceinline__ void mma16816(float* c, const uint32_t* a, uint32_t b0, uint32_t b1) {
    asm volatile(
        "mma.sync.aligned.m16n8k16.row.col.f32.f16.f16.f32 "
        "{%0,%1,%2,%3}, {%4,%5,%6,%7}, {%8,%9}, {%0,%1,%2,%3};"
        : "+f"(c[0]), "+f"(c[1]), "+f"(c[2]), "+f"(c[3])
        : "r"(a[0]), "r"(a[1]), "r"(a[2]), "r"(a[3]), "r"(b0), "r"(b1));
}
// release/acquire primitives (no full membar)
__device__ __forceinline__ void red_release_add(unsigned* p, unsigned v) {
    asm volatile("red.release.gpu.global.add.u32 [%0], %1;" :: "l"(p), "r"(v) : "memory");
}
__device__ __forceinline__ unsigned ld_acquire(const unsigned* p) {
    unsigned v;
    asm volatile("ld.acquire.gpu.global.u32 %0, [%1];" : "=r"(v) : "l"(p) : "memory");
    return v;
}
// fast transcendental (MUFU.EX2 based); per-op rel err ~1e-6
__device__ __forceinline__ float fsigm(float v) {
    return __fdividef(1.0f, 1.0f + __expf(-v));
}
__device__ __forceinline__ float ftanh(float v) {
    v = fminf(fmaxf(v, -15.0f), 15.0f);
    float e = __expf(2.0f * v);
    return __fdividef(e - 1.0f, e + 1.0f);
}

// -------------------------- init / prep kernels -----------------------------
__global__ void init_state(uint32_t* h0, const float* __restrict__ x,
                           float* __restrict__ xT) {
    int i = blockIdx.x * 256 + threadIdx.x;
    if (i < BATCH * HID / 2) h0[i] = 0u;
    if (i < TSTEPS * BATCH) {
        int t = i >> 9, b = i & 511;         // xT[t*512+b] = x[b*256+t]
        xT[i] = x[b * TSTEPS + t];
    }
    if (i < 4) g_cnt[i] = 0u;
}

// Convert W_hh to fp16 with per-column gate interleave:
//   old row r = q*512 + col, col = jn*16 + s  ->  new row = jn*64 + s*4 + q
__global__ void wprep(const float* __restrict__ Whh,
                      const float* __restrict__ b_ih, const float* __restrict__ b_hh,
                      const float* __restrict__ Wih,
                      __half* __restrict__ wh,
                      float* __restrict__ br, float* __restrict__ wihr)
{
    int i = blockIdx.x * 256 + threadIdx.x;
    if (i >= G4 * HID) return;
    int old_r = i / HID;
    int k = i - old_r * HID;
    int q = old_r >> 9;
    int col = old_r & 511;
    int jn = col >> 4;
    int s = col & 15;
    int new_r = jn * 64 + s * 4 + q;
    wh[new_r * HID + k] = __float2half(Whh[i]);
    if (k == 0) {
        br[new_r] = b_ih[old_r] + b_hh[old_r];
        wihr[new_r] = Wih[old_r];
    }
}

// ----------------------- persistent encoder kernel --------------------------
__global__ __launch_bounds__(256, 1)
void lstm_persist(const __half* __restrict__ wh,
                  const float* __restrict__ br, const float* __restrict__ wihr,
                  const float* __restrict__ xT,
                  __half* __restrict__ h0g, __half* __restrict__ h1g,
                  float* __restrict__ hf, float* __restrict__ cg,
                  float* __restrict__ G0)
{
    extern __shared__ __align__(16) char smem[];
    const uint32_t sb = smem_u32(smem);
    const int tid = threadIdx.x;
    const int wid = tid >> 5;             // 0..7
    const int l = tid & 31;
    const int wm = wid & 3;               // 0..3: 32-row m tile
    const int wn = wid >> 2;              // 0..1: 32-col n tile
    const int jn = blockIdx.x & 31;       // 0..31 (16 logical cols each)
    const int mg = blockIdx.x >> 5;       // 0..3  m-group (128 rows each)
    const int m0 = mg * TM;
    const int n0 = jn * TNR;              // reordered W row base

    // ---- load resident B slice (64 rows x 512 k), 8 chunks of 64 k ----
#pragma unroll
    for (int it = 0; it < 16; ++it) {
        int slot = tid + it * 256;        // 0..4095
        int seg = slot & 7;
        int r = (slot >> 3) & 63;
        int kc = slot >> 9;
        cpasync16(sb + (uint32_t)(kc * BCHUNK + r * PITCH + seg * 16),
                  (const char*)wh + ((size_t)(n0 + r) * HID + kc * 64) * 2 + seg * 16);
    }
    cpasync_commit();
    cpasync_wait<0>();
    __syncthreads();

    // per-lane ldmatrix byte offsets
    const uint32_t aoff = (uint32_t)((l & 15) * PITCH + (l >> 4) * 16);
    const uint32_t boff = (uint32_t)(((l & 7) + ((l >> 4) << 3)) * PITCH + ((l >> 3) & 1) * 16);

    // epilogue cell mapping (fixed across steps): c in registers, 2 m-subtiles
    const int erl0 = wm * 32 + (l >> 2) + ((l & 1) ? 8 : 0);  // local row, mt=0
    float creg[2][4] = {{0.f,0.f,0.f,0.f},{0.f,0.f,0.f,0.f}};

    // preload per-thread bias / W_ih constants (fixed across steps)
    float4 bqr[4], wqr[4];
    int scolr[4];
#pragma unroll
    for (int nt = 0; nt < 4; ++nt) {
        int scol = wn * 8 + nt * 2 + ((l & 3) >> 1);          // 0..15
        scolr[nt] = scol;
        bqr[nt] = *reinterpret_cast<const float4*>(&br[n0 + scol * 4]);
        wqr[nt] = *reinterpret_cast<const float4*>(&wihr[n0 + scol * 4]);
    }

    unsigned* cnt = &g_cnt[mg];
    __half* shh = reinterpret_cast<__half*>(smem + HOFF);

#pragma unroll 1
    for (int t = 0; t <= TSTEPS; ++t) {
        const __half* hin = (t & 1) ? h1g : h0g;
        __half* hout      = (t & 1) ? h0g : h1g;

        // ---- stage full A (128 x 512) in two halves (4 chunks each) ----
#pragma unroll
        for (int half = 0; half < 2; ++half) {
#pragma unroll
            for (int it = 0; it < 16; ++it) {
                int slot = tid + it * 256;           // 0..4095
                int seg = slot & 7;
                int r = (slot >> 3) & 127;
                int kc = half * 4 + (slot >> 10);
                cpasync16(sb + AOFF + (uint32_t)(kc * ACHUNK + r * PITCH + seg * 16),
                          (const char*)hin + ((size_t)(m0 + r) * HID + kc * 64) * 2 + seg * 16);
            }
            cpasync_commit();
        }

        float acc[2][4][4];
#pragma unroll
        for (int mt = 0; mt < 2; ++mt)
#pragma unroll
            for (int nt = 0; nt < 4; ++nt)
#pragma unroll
                for (int v = 0; v < 4; ++v) acc[mt][nt][v] = 0.0f;

        // ---- MMA: half 0 while half 1 lands, then half 1 ----
#pragma unroll
        for (int half = 0; half < 2; ++half) {
            if (half == 0) cpasync_wait<1>(); else cpasync_wait<0>();
            __syncthreads();
#pragma unroll
            for (int kci = 0; kci < 4; ++kci) {
                int kc = half * 4 + kci;
                const uint32_t stA = sb + AOFF + (uint32_t)(kc * ACHUNK + wm * 32 * PITCH);
                const uint32_t stB = sb + (uint32_t)(kc * BCHUNK + wn * 32 * PITCH);
#pragma unroll
                for (int ks = 0; ks < 4; ++ks) {
                    const uint32_t ka = (uint32_t)(ks * 32);   // 16 fp16 = 32B
                    uint32_t ar[2][4], bb[2][4];
                    ldsm_x4(ar[0], stA + ka + aoff);
                    ldsm_x4(ar[1], stA + (uint32_t)(16 * PITCH) + ka + aoff);
                    ldsm_x4(bb[0], stB + ka + boff);
                    ldsm_x4(bb[1], stB + (uint32_t)(16 * PITCH) + ka + boff);
#pragma unroll
                    for (int mt = 0; mt < 2; ++mt) {
                        mma16816(acc[mt][0], ar[mt], bb[0][0], bb[0][1]);
                        mma16816(acc[mt][1], ar[mt], bb[0][2], bb[0][3]);
                        mma16816(acc[mt][2], ar[mt], bb[1][0], bb[1][1]);
                        mma16816(acc[mt][3], ar[mt], bb[1][2], bb[1][3]);
                    }
                }
            }
        }

        // ---------------- register epilogue (shfl gate gather) ---------------
        // acc[mt][nt] col n_local = wn*32 + nt*8 + (l&3)*2 (+1) = s*4 + q.
        // Lanes l, l^1 hold (i,f)/(g,o) of the same logical column.
        if (t < TSTEPS) {
#pragma unroll
            for (int mt = 0; mt < 2; ++mt) {
                const int erl = erl0 + mt * 16;
                const int erow = m0 + erl;
                const float xv = xT[t * BATCH + erow];
#pragma unroll
                for (int nt = 0; nt < 4; ++nt) {
                    float p0 = __shfl_xor_sync(0xffffffffu, acc[mt][nt][0], 1);
                    float p1 = __shfl_xor_sync(0xffffffffu, acc[mt][nt][1], 1);
                    float p2 = __shfl_xor_sync(0xffffffffu, acc[mt][nt][2], 1);
                    float p3 = __shfl_xor_sync(0xffffffffu, acc[mt][nt][3], 1);
                    float gi, gf, gg, go;
                    if ((l & 1) == 0) { gi = acc[mt][nt][0]; gf = acc[mt][nt][1]; gg = p0; go = p1; }
                    else              { gi = p2; gf = p3; gg = acc[mt][nt][2]; go = acc[mt][nt][3]; }
                    gi += bqr[nt].x + xv * wqr[nt].x;
                    gf += bqr[nt].y + xv * wqr[nt].y;
                    gg += bqr[nt].z + xv * wqr[nt].z;
                    go += bqr[nt].w + xv * wqr[nt].w;
                    float cn = fsigm(gf) * creg[mt][nt] + fsigm(gi) * ftanh(gg);
                    creg[mt][nt] = cn;
                    float hv = fsigm(go) * ftanh(cn);
                    shh[erl * 16 + scolr[nt]] = __float2half(hv);
                    if (t == TSTEPS - 1) {
                        int idx = erow * HID + jn * 16 + scolr[nt];
                        hf[idx] = hv; cg[idx] = cn;
                    }
                }
            }
            __syncthreads();
            // coalesced copy-out: 128 rows x 16 halfs (32B/row), 512 x 8B STG
#pragma unroll
            for (int it = 0; it < 2; ++it) {
                int slot = tid + it * 256;      // 0..511
                int r = slot >> 2, seg = slot & 3;
                *reinterpret_cast<uint64_t*>(&hout[(m0 + r) * HID + jn * 16 + seg * 4]) =
                    *reinterpret_cast<const uint64_t*>(smem + HOFF + r * 32 + seg * 8);
            }
            // ---- group barrier (32 CTAs sharing m-group) ----
            __syncthreads();
            if (tid == 0) {
                red_release_add(cnt, 1u);
                unsigned target = 32u * (unsigned)(t + 1);
                while (ld_acquire(cnt) < target) { }
            }
            __syncthreads();
        } else {
            // G0 mode: gates + bias (no x term), gate-major layout
#pragma unroll
            for (int mt = 0; mt < 2; ++mt) {
                const int erow = m0 + erl0 + mt * 16;
#pragma unroll
                for (int nt = 0; nt < 4; ++nt) {
                    float p0 = __shfl_xor_sync(0xffffffffu, acc[mt][nt][0], 1);
                    float p1 = __shfl_xor_sync(0xffffffffu, acc[mt][nt][1], 1);
                    float p2 = __shfl_xor_sync(0xffffffffu, acc[mt][nt][2], 1);
                    float p3 = __shfl_xor_sync(0xffffffffu, acc[mt][nt][3], 1);
                    float gi, gf, gg, go;
                    if ((l & 1) == 0) { gi = acc[mt][nt][0]; gf = acc[mt][nt][1]; gg = p0; go = p1; }
                    else              { gi = p2; gf = p3; gg = acc[mt][nt][2]; go = acc[mt][nt][3]; }
                    int gcol = jn * 16 + scolr[nt];
                    size_t base = (size_t)erow * G4;
                    G0[base + 0 * HID + gcol] = gi + bqr[nt].x;
                    G0[base + 1 * HID + gcol] = gf + bqr[nt].y;
                    G0[base + 2 * HID + gcol] = gg + bqr[nt].z;
                    G0[base + 3 * HID + gcol] = go + bqr[nt].w;
                }
            }
        }
    }
}

// ------------------------------- decoder ------------------------------------
__global__ __launch_bounds__(256)
void decode_kernel(const float* __restrict__ hidden,
                   const float* __restrict__ cell,
                   const float* __restrict__ G0,
                   const float* __restrict__ Wih,
                   const float* __restrict__ Wout,
                   const float* __restrict__ bout,
                   float* __restrict__ out)
{
    const int b = blockIdx.x;
    const int t = threadIdx.x;

    __shared__ float sh[HID];
    __shared__ float red[9];

    float g0[2][4], wv[2][4], cc[2], wo[2];
#pragma unroll
    for (int s = 0; s < 2; ++s) {
        int jj = t + s * 256;
#pragma unroll
        for (int q = 0; q < 4; ++q) {
            g0[s][q] = G0[b * G4 + q * HID + jj];
            wv[s][q] = Wih[q * HID + jj];
        }
        cc[s] = cell[b * HID + jj];
        wo[s] = Wout[jj];
        sh[jj] = hidden[b * HID + jj];
    }
    const float bo = bout[0];
    __syncthreads();

    for (int step = 0; step < DEC_STEPS; ++step) {
        float p = sh[t] * wo[0] + sh[t + 256] * wo[1];
#pragma unroll
        for (int o = 16; o > 0; o >>= 1)
            p += __shfl_down_sync(0xffffffffu, p, o);
        if ((t & 31) == 0) red[t >> 5] = p;
        __syncthreads();
        if (t < 8) {
            float v = red[t];
            v += __shfl_down_sync(0x000000ffu, v, 4);
            v += __shfl_down_sync(0x000000ffu, v, 2);
            v += __shfl_down_sync(0x000000ffu, v, 1);
            if (t == 0) red[8] = v + bo;
        }
        __syncthreads();
        const float ov = red[8];
        if (t == 0) out[b * DEC_STEPS + step] = ov;

        float hn[2];
#pragma unroll
        for (int s = 0; s < 2; ++s) {
            float gi = g0[s][0] + ov * wv[s][0];
            float gf = g0[s][1] + ov * wv[s][1];
            float gg = g0[s][2] + ov * wv[s][2];
            float go = g0[s][3] + ov * wv[s][3];
            float cn = fsigm(gf) * cc[s] + fsigm(gi) * ftanh(gg);
            hn[s] = fsigm(go) * ftanh(cn);
        }
        __syncthreads();
        sh[t]       = hn[0];
        sh[t + 256] = hn[1];
        __syncthreads();
    }
}

// ------------------------------- launch -------------------------------------
extern "C" void kernel_launch(void* const* d_in, const int* in_sizes, int n_in,
                              void* d_out, int out_size)
{
    const float* x     = (const float*)d_in[0];
    const float* W_ih  = (const float*)d_in[1];
    const float* W_hh  = (const float*)d_in[2];
    const float* b_ih  = (const float*)d_in[3];
    const float* b_hh  = (const float*)d_in[4];
    const float* W_out = (const float*)d_in[5];
    const float* b_out = (const float*)d_in[6];
    float* out = (float*)d_out;

    __half *wh, *h0, *h1;
    float *xT, *hf, *c, *G0, *br, *wihr;
    cudaGetSymbolAddress((void**)&wh, g_wh);
    cudaGetSymbolAddress((void**)&h0, g_h0);
    cudaGetSymbolAddress((void**)&h1, g_h1);
    cudaGetSymbolAddress((void**)&xT, g_xT);
    cudaGetSymbolAddress((void**)&hf, g_hf);
    cudaGetSymbolAddress((void**)&c,  g_c);
    cudaGetSymbolAddress((void**)&G0, g_G0);
    cudaGetSymbolAddress((void**)&br, g_br);
    cudaGetSymbolAddress((void**)&wihr, g_wihr);

    cudaFuncSetAttribute(lstm_persist, cudaFuncAttributeMaxDynamicSharedMemorySize, SMEM_TOTAL);

    init_state<<<(BATCH * HID / 2 + 255) / 256, 256>>>((uint32_t*)h0, x, xT);
    wprep<<<(G4 * HID + 255) / 256, 256>>>(W_hh, b_ih, b_hh, W_ih, wh, br, wihr);

    // 128 CTAs, 1/SM (smem-forced) -> all resident; 4 counter barrier groups
    lstm_persist<<<128, 256, SMEM_TOTAL>>>(wh, br, wihr, xT, h0, h1, hf, c, G0);

    decode_kernel<<<BATCH, 256>>>(hf, c, G0, W_ih, W_out, b_out, out);
}